// round 3
// baseline (speedup 1.0000x reference)
#include <cuda_runtime.h>
#include <cuda_bf16.h>
#include <math.h>

// Problem constants
#define BB 4
#define SS 2048
#define EE 256
#define HH 8
#define DK 32
#define MM (BB * SS)   // 8192 rows for the projection GEMMs
#define KK EE          // 256
#define NN EE          // 256

// Scratch (device globals; no allocation allowed)
__device__ float g_qh[BB * HH * SS * DK];   // [B,H,S,DK]
__device__ float g_kh[BB * HH * SS * DK];
__device__ float g_vh[BB * HH * SS * DK];
__device__ float g_ao[BB * SS * EE];        // attention output in [B,S,H*DK] layout

// ---------------------------------------------------------------------------
// GEMM: C[M,N] = X[M,K] @ W[N,K]^T + bias[N]
// permute==1: scatter to [B,H,S,DK]; permute==0: row-major [M,N]
// Tiles: 64x64, K-tile 16, 256 threads, 4x4 per thread.
// ---------------------------------------------------------------------------
__global__ void gemm_bias_kernel(const float* __restrict__ X,
                                 const float* __restrict__ W,
                                 const float* __restrict__ bias,
                                 float* __restrict__ out,
                                 int permute)
{
    __shared__ float Xs[16][65];
    __shared__ float Ws[16][65];

    const int tid = threadIdx.x;
    const int tx = tid & 15;        // 0..15 -> 4 output cols each
    const int ty = tid >> 4;        // 0..15 -> 4 output rows each
    const int m0 = blockIdx.x * 64;
    const int n0 = blockIdx.y * 64;

    float acc[4][4];
#pragma unroll
    for (int x = 0; x < 4; x++)
#pragma unroll
        for (int y = 0; y < 4; y++) acc[x][y] = 0.f;

    for (int t = 0; t < KK / 16; t++) {
        const int k0 = t * 16;
#pragma unroll
        for (int l = 0; l < 4; l++) {
            int e = tid + l * 256;
            int r = e >> 4;
            int c = e & 15;
            Xs[c][r] = X[(size_t)(m0 + r) * KK + k0 + c];
            Ws[c][r] = W[(size_t)(n0 + r) * KK + k0 + c];
        }
        __syncthreads();
#pragma unroll
        for (int kk = 0; kk < 16; kk++) {
            float a[4], b[4];
#pragma unroll
            for (int x = 0; x < 4; x++) {
                a[x] = Xs[kk][ty * 4 + x];
                b[x] = Ws[kk][tx * 4 + x];
            }
#pragma unroll
            for (int x = 0; x < 4; x++)
#pragma unroll
                for (int y = 0; y < 4; y++) acc[x][y] += a[x] * b[y];
        }
        __syncthreads();
    }

#pragma unroll
    for (int x = 0; x < 4; x++) {
#pragma unroll
        for (int y = 0; y < 4; y++) {
            int m = m0 + ty * 4 + x;
            int n = n0 + tx * 4 + y;
            float val = acc[x][y] + bias[n];
            if (permute) {
                int b_ = m >> 11;        // m / 2048
                int s_ = m & 2047;
                int h_ = n >> 5;         // n / 32
                int d_ = n & 31;
                out[(((size_t)b_ * HH + h_) * SS + s_) * DK + d_] = val;
            } else {
                out[(size_t)m * NN + n] = val;
            }
        }
    }
}

// ---------------------------------------------------------------------------
// Attention with distance-decay: one block per (b,h,i) row, 256 threads.
// ---------------------------------------------------------------------------
__global__ void attn_decay_kernel(const float* __restrict__ qh,
                                  const float* __restrict__ kh,
                                  const float* __restrict__ vh,
                                  const float* __restrict__ gammas,
                                  float* __restrict__ ao)
{
    __shared__ float sc[SS];       // raw scores (kept for second pass)
    __shared__ float w[SS];        // s1 / cumsum / rescaled scores / attn
    __shared__ float qs[DK];
    __shared__ float red[256];
    __shared__ float wred[8][33];

    const int tid = threadIdx.x;
    const int row = blockIdx.x;            // b*H*S + h*S + i
    const int i = row & (SS - 1);
    const int bh = row >> 11;              // row / SS
    const int h = bh & (HH - 1);
    const int b = bh >> 3;                 // bh / HH
    const int L = i + 1;

    const float* kbase = kh + (size_t)bh * SS * DK;
    const float* vbase = vh + (size_t)bh * SS * DK;
    const float* qrow = qh + (size_t)row * DK;

    // gamma = -softplus(gammas[h])
    const float g = gammas[h];
    const float gamma = -log1pf(__expf(g));
    const float scale = rsqrtf((float)DK);

    if (tid < DK) qs[tid] = qrow[tid];
    __syncthreads();

    // --- scores[j] = q . k_j * scale, j in [0, L) ---
    for (int j = tid; j < L; j += 256) {
        const float4* kr = (const float4*)(kbase + (size_t)j * DK);
        float dot = 0.f;
#pragma unroll
        for (int t = 0; t < 8; t++) {
            float4 kv = kr[t];
            dot += qs[4 * t + 0] * kv.x + qs[4 * t + 1] * kv.y +
                   qs[4 * t + 2] * kv.z + qs[4 * t + 3] * kv.w;
        }
        sc[j] = dot * scale;
    }
    __syncthreads();

    // --- softmax #1 -> s1 in w ---
    float m1 = -3.402823e38f;
    for (int j = tid; j < L; j += 256) m1 = fmaxf(m1, sc[j]);
    red[tid] = m1;
    __syncthreads();
    for (int s = 128; s > 0; s >>= 1) {
        if (tid < s) red[tid] = fmaxf(red[tid], red[tid + s]);
        __syncthreads();
    }
    const float rowmax = red[0];
    __syncthreads();

    float lsum = 0.f;
    for (int j = tid; j < L; j += 256) {
        float e = __expf(sc[j] - rowmax);
        w[j] = e;
        lsum += e;
    }
    red[tid] = lsum;
    __syncthreads();
    for (int s = 128; s > 0; s >>= 1) {
        if (tid < s) red[tid] += red[tid + s];
        __syncthreads();
    }
    const float inv1 = 1.f / red[0];
    __syncthreads();
    for (int j = tid; j < L; j += 256) w[j] *= inv1;
    __syncthreads();

    // --- inclusive cumsum of w[0..L) (chunked + block scan of totals) ---
    const int chunk = (L + 255) >> 8;
    const int beg = tid * chunk;
    const int end = min(beg + chunk, L);
    float run = 0.f;
    for (int j = beg; j < end; j++) {
        run += w[j];
        w[j] = run;
    }
    red[tid] = run;
    __syncthreads();
    for (int off = 1; off < 256; off <<= 1) {
        float val = red[tid];
        float add = (tid >= off) ? red[tid - off] : 0.f;
        __syncthreads();
        red[tid] = val + add;
        __syncthreads();
    }
    const float total = red[255];
    const float excl = red[tid] - run;
    __syncthreads();
    for (int j = beg; j < end; j++) w[j] += excl;
    __syncthreads();

    // --- dist/effect, rescaled scores into w ---
    for (int j = tid; j < L; j += 256) {
        float rem = total - w[j];
        float dist = sqrtf(fmaxf(rem * (float)(i - j), 0.f));
        float eff = __expf(dist * gamma);
        eff = fminf(fmaxf(eff, 1e-5f), 1e5f);
        w[j] = sc[j] * eff;
    }
    __syncthreads();

    // --- softmax #2 -> attn in w ---
    float m2 = -3.402823e38f;
    for (int j = tid; j < L; j += 256) m2 = fmaxf(m2, w[j]);
    red[tid] = m2;
    __syncthreads();
    for (int s = 128; s > 0; s >>= 1) {
        if (tid < s) red[tid] = fmaxf(red[tid], red[tid + s]);
        __syncthreads();
    }
    const float rowmax2 = red[0];
    __syncthreads();

    float lsum2 = 0.f;
    for (int j = tid; j < L; j += 256) {
        float e = __expf(w[j] - rowmax2);
        w[j] = e;
        lsum2 += e;
    }
    red[tid] = lsum2;
    __syncthreads();
    for (int s = 128; s > 0; s >>= 1) {
        if (tid < s) red[tid] += red[tid + s];
        __syncthreads();
    }
    const float inv2 = 1.f / red[0];
    __syncthreads();

    // --- out = attn @ V ---
    float acc[DK];
#pragma unroll
    for (int d = 0; d < DK; d++) acc[d] = 0.f;
    for (int j = tid; j < L; j += 256) {
        float a = w[j] * inv2;
        const float4* vr = (const float4*)(vbase + (size_t)j * DK);
#pragma unroll
        for (int t = 0; t < 8; t++) {
            float4 vv = vr[t];
            acc[4 * t + 0] += a * vv.x;
            acc[4 * t + 1] += a * vv.y;
            acc[4 * t + 2] += a * vv.z;
            acc[4 * t + 3] += a * vv.w;
        }
    }

    const int lane = tid & 31;
    const int wrp = tid >> 5;
#pragma unroll
    for (int d = 0; d < DK; d++) {
        float v_ = acc[d];
#pragma unroll
        for (int off = 16; off > 0; off >>= 1)
            v_ += __shfl_down_sync(0xffffffff, v_, off);
        if (lane == 0) wred[wrp][d] = v_;
    }
    __syncthreads();
    if (tid < DK) {
        float s_ = 0.f;
#pragma unroll
        for (int ww = 0; ww < 8; ww++) s_ += wred[ww][tid];
        // concat layout: [b, i, h*DK + d]
        ao[((size_t)b * SS + i) * EE + h * DK + tid] = s_;
    }
}

// ---------------------------------------------------------------------------
extern "C" void kernel_launch(void* const* d_in, const int* in_sizes, int n_in,
                              void* d_out, int out_size)
{
    const float* q      = (const float*)d_in[0];
    const float* k      = (const float*)d_in[1];
    const float* v      = (const float*)d_in[2];
    // d_in[3] = mask (unused; causal structure is known)
    const float* Wq     = (const float*)d_in[4];
    const float* bq     = (const float*)d_in[5];
    const float* Wk     = (const float*)d_in[6];
    const float* bk     = (const float*)d_in[7];
    const float* Wv     = (const float*)d_in[8];
    const float* bv     = (const float*)d_in[9];
    const float* Wo     = (const float*)d_in[10];
    const float* bo     = (const float*)d_in[11];
    const float* gammas = (const float*)d_in[12];
    float* out = (float*)d_out;

    float *qh, *kh, *vh, *ao;
    cudaGetSymbolAddress((void**)&qh, g_qh);
    cudaGetSymbolAddress((void**)&kh, g_kh);
    cudaGetSymbolAddress((void**)&vh, g_vh);
    cudaGetSymbolAddress((void**)&ao, g_ao);

    dim3 gblk(256);
    dim3 ggrid(MM / 64, NN / 64);

    gemm_bias_kernel<<<ggrid, gblk>>>(q, Wq, bq, qh, 1);
    gemm_bias_kernel<<<ggrid, gblk>>>(k, Wk, bk, kh, 1);
    gemm_bias_kernel<<<ggrid, gblk>>>(v, Wv, bv, vh, 1);

    attn_decay_kernel<<<BB * HH * SS, 256>>>(qh, kh, vh, gammas, ao);

    gemm_bias_kernel<<<ggrid, gblk>>>(ao, Wo, bo, out, 0);
}

// round 5
// speedup vs baseline: 6.5715x; 6.5715x over previous
#include <cuda_runtime.h>
#include <cuda_bf16.h>
#include <math.h>

// Problem constants
#define BB 4
#define SS 2048
#define EE 256
#define HH 8
#define DK 32
#define MM (BB * SS)
#define KK EE
#define NN EE

#define QT 128            // query tile rows per block
#define JT 64             // key tile cols per iteration
#define NQT (SS / QT)     // 16 query tiles

// Scratch (device globals; no allocation allowed)
__device__ float g_qh[BB * HH * SS * DK];   // [B,H,S,DK]
__device__ float g_kh[BB * HH * SS * DK];
__device__ float g_vh[BB * HH * SS * DK];
__device__ float g_ao[BB * SS * EE];        // attention output [B,S,H*DK]

// ---------------------------------------------------------------------------
// GEMM: C[M,N] = X[M,K] @ W[N,K]^T + bias[N]
// ---------------------------------------------------------------------------
__global__ void gemm_bias_kernel(const float* __restrict__ X,
                                 const float* __restrict__ W,
                                 const float* __restrict__ bias,
                                 float* __restrict__ out,
                                 int permute)
{
    __shared__ float Xs[16][65];
    __shared__ float Ws[16][65];

    const int tid = threadIdx.x;
    const int tx = tid & 15;
    const int ty = tid >> 4;
    const int m0 = blockIdx.x * 64;
    const int n0 = blockIdx.y * 64;

    float acc[4][4];
#pragma unroll
    for (int x = 0; x < 4; x++)
#pragma unroll
        for (int y = 0; y < 4; y++) acc[x][y] = 0.f;

    for (int t = 0; t < KK / 16; t++) {
        const int k0 = t * 16;
#pragma unroll
        for (int l = 0; l < 4; l++) {
            int e = tid + l * 256;
            int r = e >> 4;
            int c = e & 15;
            Xs[c][r] = X[(size_t)(m0 + r) * KK + k0 + c];
            Ws[c][r] = W[(size_t)(n0 + r) * KK + k0 + c];
        }
        __syncthreads();
#pragma unroll
        for (int kk = 0; kk < 16; kk++) {
            float a[4], b[4];
#pragma unroll
            for (int x = 0; x < 4; x++) {
                a[x] = Xs[kk][ty * 4 + x];
                b[x] = Ws[kk][tx * 4 + x];
            }
#pragma unroll
            for (int x = 0; x < 4; x++)
#pragma unroll
                for (int y = 0; y < 4; y++) acc[x][y] += a[x] * b[y];
        }
        __syncthreads();
    }

#pragma unroll
    for (int x = 0; x < 4; x++) {
#pragma unroll
        for (int y = 0; y < 4; y++) {
            int m = m0 + ty * 4 + x;
            int n = n0 + tx * 4 + y;
            float val = acc[x][y] + bias[n];
            if (permute) {
                int b_ = m >> 11;
                int s_ = m & 2047;
                int h_ = n >> 5;
                int d_ = n & 31;
                out[(((size_t)b_ * HH + h_) * SS + s_) * DK + d_] = val;
            } else {
                out[(size_t)m * NN + n] = val;
            }
        }
    }
}

// ---------------------------------------------------------------------------
// Tiled attention with distance-decay.
// Block: 128 query rows of one (b,h). Threads 256: tx=tid&15 (4 score cols /
// 2 out dims), ty=tid>>4 (8 rows).
// ---------------------------------------------------------------------------
struct AttnSmem {
    float Qs[32][132];    // [k][r]  query tile, transposed
    float Ks[32][68];     // [k][c]  key tile, transposed
    float Vst[32][68];    // [d][c]  value tile, transposed
    float ps[128][68];    // scratch: prefix vals, then p2 tile
    float rowbuf[128][17];// per-row cross-thread reductions / scan
    float m1s[128];
    float s1s[128];
    float m2s[128];
    float l2s[128];
    float carry[128];
    float fac[128];
};

__device__ __forceinline__ void compute_scores(
    const AttnSmem* S, int r0, int c0, int i0, int j0,
    float scale, float scr[8][4])
{
#pragma unroll
    for (int y = 0; y < 8; y++)
#pragma unroll
        for (int x = 0; x < 4; x++) scr[y][x] = 0.f;

#pragma unroll
    for (int k = 0; k < 32; k++) {
        float4 a0 = *(const float4*)&S->Qs[k][r0];
        float4 a1 = *(const float4*)&S->Qs[k][r0 + 4];
        float4 bb = *(const float4*)&S->Ks[k][c0];
        float a[8] = {a0.x, a0.y, a0.z, a0.w, a1.x, a1.y, a1.z, a1.w};
        float b[4] = {bb.x, bb.y, bb.z, bb.w};
#pragma unroll
        for (int y = 0; y < 8; y++)
#pragma unroll
            for (int x = 0; x < 4; x++) scr[y][x] += a[y] * b[x];
    }
    // scale + causal mask
    bool need_mask = (j0 + JT - 1 > i0);
#pragma unroll
    for (int y = 0; y < 8; y++) {
        int i = i0 + r0 + y;
#pragma unroll
        for (int x = 0; x < 4; x++) {
            scr[y][x] *= scale;
            if (need_mask && (j0 + c0 + x > i)) scr[y][x] = -1e30f;
        }
    }
}

__global__ __launch_bounds__(256, 2)
void attn_tile_kernel(const float* __restrict__ qh,
                      const float* __restrict__ kh,
                      const float* __restrict__ vh,
                      const float* __restrict__ gammas,
                      float* __restrict__ ao)
{
    extern __shared__ char smem_raw[];
    AttnSmem* S = (AttnSmem*)smem_raw;

    const int tid = threadIdx.x;
    const int tx = tid & 15;
    const int ty = tid >> 4;
    const int r0 = ty * 8;
    const int c0 = tx * 4;

    // heavy q-tiles launch first
    const int qt = (NQT - 1) - (blockIdx.x >> 5);
    const int bh = blockIdx.x & 31;
    const int h = bh & (HH - 1);
    const int b = bh >> 3;
    const int i0 = qt * QT;
    const int jtiles = 2 * qt + 2;

    const float* qbase = qh + (size_t)bh * SS * DK;
    const float* kbase = kh + (size_t)bh * SS * DK;
    const float* vbase = vh + (size_t)bh * SS * DK;

    const float g = gammas[h];
    const float gamma = -log1pf(__expf(g));
    const float scale = 0.17677669529663687f;  // 1/sqrt(32)

    // ---- load Q tile (transposed) ----
#pragma unroll
    for (int l = 0; l < 4; l++) {
        int idx = tid + l * 256;
        int r = idx >> 3;
        int kq = (idx & 7) * 4;
        float4 qv = *(const float4*)(qbase + (size_t)(i0 + r) * DK + kq);
        S->Qs[kq + 0][r] = qv.x;
        S->Qs[kq + 1][r] = qv.y;
        S->Qs[kq + 2][r] = qv.z;
        S->Qs[kq + 3][r] = qv.w;
    }
    if (tid < QT) {
        S->m1s[tid] = -3.0e38f;
        S->s1s[tid] = 0.f;
        S->m2s[tid] = -3.0e38f;
        S->l2s[tid] = 0.f;
        S->carry[tid] = 0.f;
    }
    __syncthreads();

    float scr[8][4];

    // =================== PASS 1: softmax-1 stats ===================
    for (int jt = 0; jt < jtiles; jt++) {
        const int j0 = jt * JT;
        __syncthreads();  // protect Ks reuse + rowbuf
#pragma unroll
        for (int l = 0; l < 2; l++) {
            int idx = tid + l * 256;
            int c = idx >> 3;
            int kq = (idx & 7) * 4;
            float4 kv = *(const float4*)(kbase + (size_t)(j0 + c) * DK + kq);
            S->Ks[kq + 0][c] = kv.x;
            S->Ks[kq + 1][c] = kv.y;
            S->Ks[kq + 2][c] = kv.z;
            S->Ks[kq + 3][c] = kv.w;
        }
        __syncthreads();

        compute_scores(S, r0, c0, i0, j0, scale, scr);

#pragma unroll
        for (int y = 0; y < 8; y++) {
            float lm = fmaxf(fmaxf(scr[y][0], scr[y][1]), fmaxf(scr[y][2], scr[y][3]));
            S->rowbuf[r0 + y][tx] = lm;
        }
        __syncthreads();
        if (tid < QT) {
            int r = tid;
            float tm = -3.0e38f;
#pragma unroll
            for (int t = 0; t < 16; t++) tm = fmaxf(tm, S->rowbuf[r][t]);
            float nm = fmaxf(S->m1s[r], tm);
            S->fac[r] = __expf(S->m1s[r] - nm);
            S->m1s[r] = nm;
        }
        __syncthreads();
#pragma unroll
        for (int y = 0; y < 8; y++) {
            float m = S->m1s[r0 + y];
            float pe = __expf(scr[y][0] - m) + __expf(scr[y][1] - m) +
                       __expf(scr[y][2] - m) + __expf(scr[y][3] - m);
            S->rowbuf[r0 + y][tx] = pe;
        }
        __syncthreads();
        if (tid < QT) {
            int r = tid;
            float s = 0.f;
#pragma unroll
            for (int t = 0; t < 16; t++) s += S->rowbuf[r][t];
            S->s1s[r] = S->s1s[r] * S->fac[r] + s;
        }
    }
    __syncthreads();

    // per-thread row stats in registers
    float rm1[8], ri1[8];
#pragma unroll
    for (int y = 0; y < 8; y++) {
        rm1[y] = S->m1s[r0 + y];
        ri1[y] = 1.f / S->s1s[r0 + y];
    }

    float acc[8][2];
#pragma unroll
    for (int y = 0; y < 8; y++) { acc[y][0] = 0.f; acc[y][1] = 0.f; }

    // =================== PASS 2: decay rescale + softmax-2 + PV ===================
    for (int jt = 0; jt < jtiles; jt++) {
        const int j0 = jt * JT;
        __syncthreads();  // previous PV done; safe to overwrite tiles
#pragma unroll
        for (int l = 0; l < 2; l++) {
            int idx = tid + l * 256;
            int c = idx >> 3;
            int kq = (idx & 7) * 4;
            float4 kv = *(const float4*)(kbase + (size_t)(j0 + c) * DK + kq);
            S->Ks[kq + 0][c] = kv.x;
            S->Ks[kq + 1][c] = kv.y;
            S->Ks[kq + 2][c] = kv.z;
            S->Ks[kq + 3][c] = kv.w;
            float4 vv = *(const float4*)(vbase + (size_t)(j0 + c) * DK + kq);
            S->Vst[kq + 0][c] = vv.x;
            S->Vst[kq + 1][c] = vv.y;
            S->Vst[kq + 2][c] = vv.z;
            S->Vst[kq + 3][c] = vv.w;
        }
        __syncthreads();

        compute_scores(S, r0, c0, i0, j0, scale, scr);

        // s1 chunk prefix (inclusive) -> ps, chunk totals -> rowbuf
#pragma unroll
        for (int y = 0; y < 8; y++) {
            float m = rm1[y], is = ri1[y];
            float e0 = __expf(scr[y][0] - m) * is;
            float e1 = __expf(scr[y][1] - m) * is;
            float e2 = __expf(scr[y][2] - m) * is;
            float e3 = __expf(scr[y][3] - m) * is;
            float p0 = e0, p1 = p0 + e1, p2 = p1 + e2, p3 = p2 + e3;
            *(float4*)&S->ps[r0 + y][c0] = make_float4(p0, p1, p2, p3);
            S->rowbuf[r0 + y][tx] = p3;
        }
        __syncthreads();
        // sequential scan of 16 chunk totals per row + carry
        if (tid < QT) {
            int r = tid;
            float run = S->carry[r];
#pragma unroll
            for (int t = 0; t < 16; t++) {
                float tmp = S->rowbuf[r][t];
                S->rowbuf[r][t] = run;
                run += tmp;
            }
            S->carry[r] = run;
        }
        __syncthreads();

        // s2 = sc * clip(exp(sqrt(clip((1-cum)*|i-j|))*gamma)) ; row max -> rowbuf
#pragma unroll
        for (int y = 0; y < 8; y++) {
            int i = i0 + r0 + y;
            float excl = S->rowbuf[r0 + y][tx];
            float4 pre = *(const float4*)&S->ps[r0 + y][c0];
            float cums[4] = {excl + pre.x, excl + pre.y, excl + pre.z, excl + pre.w};
#pragma unroll
            for (int x = 0; x < 4; x++) {
                int j = j0 + c0 + x;
                float rem = 1.f - cums[x];
                float posn = fabsf((float)(i - j));
                float dist = sqrtf(fmaxf(rem * posn, 0.f));
                float eff = __expf(dist * gamma);
                eff = fminf(fmaxf(eff, 1e-5f), 1e5f);
                scr[y][x] = scr[y][x] * eff;   // masked entries stay huge-negative
            }
            float lm = fmaxf(fmaxf(scr[y][0], scr[y][1]), fmaxf(scr[y][2], scr[y][3]));
            S->rowbuf[r0 + y][tx] = lm;
        }
        __syncthreads();
        if (tid < QT) {
            int r = tid;
            float tm = -3.0e38f;
#pragma unroll
            for (int t = 0; t < 16; t++) tm = fmaxf(tm, S->rowbuf[r][t]);
            float nm = fmaxf(S->m2s[r], tm);
            S->fac[r] = __expf(S->m2s[r] - nm);
            S->m2s[r] = nm;
        }
        __syncthreads();

        // p2 tile -> ps, row partial sums -> rowbuf, rescale accumulators
#pragma unroll
        for (int y = 0; y < 8; y++) {
            float m = S->m2s[r0 + y];
            float f = S->fac[r0 + y];
            float p0 = __expf(scr[y][0] - m);
            float p1 = __expf(scr[y][1] - m);
            float p2 = __expf(scr[y][2] - m);
            float p3 = __expf(scr[y][3] - m);
            *(float4*)&S->ps[r0 + y][c0] = make_float4(p0, p1, p2, p3);
            S->rowbuf[r0 + y][tx] = p0 + p1 + p2 + p3;
            acc[y][0] *= f;
            acc[y][1] *= f;
        }
        __syncthreads();
        if (tid < QT) {
            int r = tid;
            float s = 0.f;
#pragma unroll
            for (int t = 0; t < 16; t++) s += S->rowbuf[r][t];
            S->l2s[r] = S->l2s[r] * S->fac[r] + s;
        }
        __syncthreads();

        // PV: out[r][d] += sum_c p2[r][c] * V[c][d]
        const int d0 = 2 * tx;
#pragma unroll 4
        for (int cb = 0; cb < 16; cb++) {
            float4 v0 = *(const float4*)&S->Vst[d0][cb * 4];
            float4 v1 = *(const float4*)&S->Vst[d0 + 1][cb * 4];
#pragma unroll
            for (int y = 0; y < 8; y++) {
                float4 pp = *(const float4*)&S->ps[r0 + y][cb * 4];
                acc[y][0] += pp.x * v0.x + pp.y * v0.y + pp.z * v0.z + pp.w * v0.w;
                acc[y][1] += pp.x * v1.x + pp.y * v1.y + pp.z * v1.z + pp.w * v1.w;
            }
        }
    }

    // ---- write output ----
#pragma unroll
    for (int y = 0; y < 8; y++) {
        int i = i0 + r0 + y;
        float inv = 1.f / S->l2s[r0 + y];
        size_t base = ((size_t)b * SS + i) * EE + h * DK + 2 * tx;
        ao[base] = acc[y][0] * inv;
        ao[base + 1] = acc[y][1] * inv;
    }
}

// ---------------------------------------------------------------------------
extern "C" void kernel_launch(void* const* d_in, const int* in_sizes, int n_in,
                              void* d_out, int out_size)
{
    const float* q      = (const float*)d_in[0];
    const float* k      = (const float*)d_in[1];
    const float* v      = (const float*)d_in[2];
    // d_in[3] = mask (unused; causal structure known)
    const float* Wq     = (const float*)d_in[4];
    const float* bq     = (const float*)d_in[5];
    const float* Wk     = (const float*)d_in[6];
    const float* bk     = (const float*)d_in[7];
    const float* Wv     = (const float*)d_in[8];
    const float* bv     = (const float*)d_in[9];
    const float* Wo     = (const float*)d_in[10];
    const float* bo     = (const float*)d_in[11];
    const float* gammas = (const float*)d_in[12];
    float* out = (float*)d_out;

    float *qh, *kh, *vh, *ao;
    cudaGetSymbolAddress((void**)&qh, g_qh);
    cudaGetSymbolAddress((void**)&kh, g_kh);
    cudaGetSymbolAddress((void**)&vh, g_vh);
    cudaGetSymbolAddress((void**)&ao, g_ao);

    static bool attr_set = false;
    if (!attr_set) {
        cudaFuncSetAttribute(attn_tile_kernel,
                             cudaFuncAttributeMaxDynamicSharedMemorySize,
                             (int)sizeof(AttnSmem));
        attr_set = true;
    }

    dim3 gblk(256);
    dim3 ggrid(MM / 64, NN / 64);

    gemm_bias_kernel<<<ggrid, gblk>>>(q, Wq, bq, qh, 1);
    gemm_bias_kernel<<<ggrid, gblk>>>(k, Wk, bk, kh, 1);
    gemm_bias_kernel<<<ggrid, gblk>>>(v, Wv, bv, vh, 1);

    attn_tile_kernel<<<BB * HH * NQT, 256, sizeof(AttnSmem)>>>(qh, kh, vh, gammas, ao);

    gemm_bias_kernel<<<ggrid, gblk>>>(ao, Wo, bo, out, 0);
}